// round 12
// baseline (speedup 1.0000x reference)
#include <cuda_runtime.h>
#include <cuda_bf16.h>
#include <cuda_fp16.h>
#include <math.h>
#include <stdint.h>

#define B_ 32
#define D_ 512
#define N_ 2048
#define K_ 64

// ---------------------------------------------------------------------------
// Scratch (static device globals; no allocations allowed)
__device__ __align__(16) __half g_Wf[K_ * D_];                      // W fp16 (64 KB)
__device__ __align__(16) __half g_Sf[(size_t)B_ * K_ * N_];         // scores fp16 (8 MB)
__device__ __align__(16) float g_ssum[B_ * K_];
__device__ __align__(16) float g_colss[B_ * K_];
__device__ __align__(16) float g_agg[(size_t)B_ * D_ * K_];         // 4 MB

// ---------------------------------------------------------------------------
__device__ __forceinline__ uint32_t smem_u32(const void* p) {
    uint32_t a;
    asm("{ .reg .u64 t; cvta.to.shared.u64 t, %1; cvt.u32.u64 %0, t; }" : "=r"(a) : "l"(p));
    return a;
}
__device__ __forceinline__ void ldsm4(uint32_t* r, uint32_t a) {
    asm volatile("ldmatrix.sync.aligned.m8n8.x4.shared.b16 {%0,%1,%2,%3}, [%4];"
                 : "=r"(r[0]), "=r"(r[1]), "=r"(r[2]), "=r"(r[3]) : "r"(a));
}
__device__ __forceinline__ void ldsm4t(uint32_t* r, uint32_t a) {
    asm volatile("ldmatrix.sync.aligned.m8n8.x4.trans.shared.b16 {%0,%1,%2,%3}, [%4];"
                 : "=r"(r[0]), "=r"(r[1]), "=r"(r[2]), "=r"(r[3]) : "r"(a));
}
__device__ __forceinline__ void mma_f16(float* c, const uint32_t* a, const uint32_t* b) {
    asm volatile("mma.sync.aligned.m16n8k16.row.col.f32.f16.f16.f32 "
                 "{%0,%1,%2,%3}, {%4,%5,%6,%7}, {%8,%9}, {%0,%1,%2,%3};"
                 : "+f"(c[0]), "+f"(c[1]), "+f"(c[2]), "+f"(c[3])
                 : "r"(a[0]), "r"(a[1]), "r"(a[2]), "r"(a[3]), "r"(b[0]), "r"(b[1]));
}
// fp16 hi/lo split of two floats
__device__ __forceinline__ void split2h(float x, float y, uint32_t& hi, uint32_t& lo) {
    __half2 h = __floats2half2_rn(x, y);
    float2 f = __half22float2(h);
    __half2 l = __floats2half2_rn(x - f.x, y - f.y);
    hi = *(uint32_t*)&h;
    lo = *(uint32_t*)&l;
}
#define CP16(dst, src) asm volatile("cp.async.cg.shared.global [%0], [%1], 16;" :: "r"(dst), "l"(src))
#define CP_COMMIT()    asm volatile("cp.async.commit_group;")
#define CP_WAIT0()     asm volatile("cp.async.wait_group 0;" ::: "memory")

// ---------------------------------------------------------------------------
__global__ void k_prep(const float* __restrict__ W) {
    int t = blockIdx.x * blockDim.x + threadIdx.x;
    if (t < B_ * K_) { g_ssum[t] = 0.f; g_colss[t] = 0.f; }
    if (t < K_ * D_ / 4) {
        float4 v = *(const float4*)&W[t * 4];
        __half2 a = __floats2half2_rn(v.x, v.y);
        __half2 b = __floats2half2_rn(v.z, v.w);
        *(uint2*)&g_Wf[t * 4] = make_uint2(*(uint32_t*)&a, *(uint32_t*)&b);
    }
}

// ---------------------------------------------------------------------------
// Kernel A: logits[64 k][128 n] = W @ x_tile (reduce D=512), fp16 2-pass:
// acc += W*x_hi + W*x_lo. W fp16 via cp.async; x split in-regs.
#define PA 40
#define PX 136
#define A_BUF  22528
#define A_ST2  34048
#define A_SMEM (34048 + 16384)

__global__ __launch_bounds__(256) void kA(const float* __restrict__ x) {
    extern __shared__ char sm[];
    const int b = blockIdx.y, n0 = blockIdx.x * 128;
    const int tid = threadIdx.x, lane = tid & 31, wid = tid >> 5;
    const int wm = wid & 3, wn = wid >> 2;
    const uint32_t smb = smem_u32(sm);

    const int wk4 = tid >> 2, wq = (tid & 3) * 8;    // W cp.async: k row, d offset(8 halfs)
    const int xnn = lane * 4;                         // x: n offset

    float acc[8][4];
#pragma unroll
    for (int i = 0; i < 8; i++)
#pragma unroll
        for (int j = 0; j < 4; j++) acc[i][j] = 0.f;

    {
        uint32_t dst = smb + wk4 * 80 + wq * 2;
        CP16(dst, &g_Wf[wk4 * D_ + wq]);
        CP_COMMIT();
    }
    float4 xbuf[4];
#pragma unroll
    for (int p = 0; p < 4; p++)
        xbuf[p] = *(const float4*)&x[((size_t)b * D_ + wid + p * 8) * N_ + n0 + xnn];

    for (int c = 0; c < 16; c++) {
        char* bufc = sm + (c & 1) * A_BUF;
        __half* Xh = (__half*)(bufc + 5120);
        __half* Xl = (__half*)(bufc + 13824);

#pragma unroll
        for (int p = 0; p < 4; p++) {
            int dd = wid + p * 8;
            uint32_t h0, l0, h1, l1;
            split2h(xbuf[p].x, xbuf[p].y, h0, l0);
            split2h(xbuf[p].z, xbuf[p].w, h1, l1);
            int off = dd * PX + xnn;
            *(uint32_t*)&Xh[off] = h0; *(uint32_t*)&Xh[off + 2] = h1;
            *(uint32_t*)&Xl[off] = l0; *(uint32_t*)&Xl[off + 2] = l1;
        }
        CP_WAIT0();
        __syncthreads();

        if (c < 15) {
            int d1 = (c + 1) * 32;
            uint32_t dst = smb + ((c + 1) & 1) * A_BUF + wk4 * 80 + wq * 2;
            CP16(dst, &g_Wf[wk4 * D_ + d1 + wq]);
            CP_COMMIT();
#pragma unroll
            for (int p = 0; p < 4; p++)
                xbuf[p] = *(const float4*)&x[((size_t)b * D_ + d1 + wid + p * 8) * N_ + n0 + xnn];
        }

        const uint32_t w_a  = smb + (c & 1) * A_BUF;
        const uint32_t xh_a = w_a + 5120;
        const uint32_t xl_a = w_a + 13824;
#pragma unroll
        for (int ks = 0; ks < 2; ks++) {
            uint32_t aw[4];
            uint32_t aoff = (uint32_t)(((wm * 16 + (lane & 15)) * PA + ks * 16 + (lane >> 4) * 8) * 2);
            ldsm4(aw, w_a + aoff);
#pragma unroll
            for (int nf = 0; nf < 4; nf++) {
                uint32_t bh[4], bl[4];
                uint32_t boff = (uint32_t)(((ks * 16 + (lane & 15)) * PX +
                                            wn * 64 + nf * 16 + (lane >> 4) * 8) * 2);
                ldsm4t(bh, xh_a + boff);
                ldsm4t(bl, xl_a + boff);
                mma_f16(acc[nf * 2],     aw, bh);
                mma_f16(acc[nf * 2],     aw, bl);
                mma_f16(acc[nf * 2 + 1], aw, bh + 2);
                mma_f16(acc[nf * 2 + 1], aw, bl + 2);
            }
        }
    }
    __syncthreads();

    // stash logits tile [64][132] f32
    float* st = (float*)sm;
    {
        int g = lane >> 2, tg = lane & 3;
        int r0 = wm * 16 + g;
#pragma unroll
        for (int nf = 0; nf < 8; nf++) {
            int cix = wn * 64 + nf * 8 + tg * 2;
            st[r0 * 132 + cix]           = acc[nf][0];
            st[r0 * 132 + cix + 1]       = acc[nf][1];
            st[(r0 + 8) * 132 + cix]     = acc[nf][2];
            st[(r0 + 8) * 132 + cix + 1] = acc[nf][3];
        }
    }
    float* ssred = (float*)(sm + 33792);
    __half* st2 = (__half*)(sm + A_ST2);
    __syncthreads();

    // softmax over k per column; quantize scores to fp16
    if (tid < 128) {
        int col = tid;
        float m = -1e30f;
#pragma unroll
        for (int k = 0; k < 64; k++) m = fmaxf(m, st[k * 132 + col]);
        float s = 0.f;
#pragma unroll
        for (int k = 0; k < 64; k++) {
            float e = __expf(st[k * 132 + col] - m);
            st[k * 132 + col] = e;
            s += e;
        }
        float inv = 1.f / s;
#pragma unroll
        for (int k = 0; k < 64; k++)
            st2[k * 128 + col] = __float2half_rn(st[k * 132 + col] * inv);
    }
    __syncthreads();

    // coalesced fp16 score writes + piggybacked per-row ssum (quantized values)
#pragma unroll
    for (int r = 0; r < 8; r++) {
        int row = wid * 8 + r;
        uint2 v = ((const uint2*)&st2[row * 128])[lane];
        ((uint2*)&g_Sf[((size_t)b * K_ + row) * N_ + n0])[lane] = v;
        __half2 h0 = *(__half2*)&v.x, h1 = *(__half2*)&v.y;
        float2 f0 = __half22float2(h0), f1 = __half22float2(h1);
        float ws = (f0.x + f0.y) + (f1.x + f1.y);
#pragma unroll
        for (int o = 16; o > 0; o >>= 1) ws += __shfl_xor_sync(0xffffffff, ws, o);
        if (lane == 0) ssred[row] = ws;
    }
    __syncthreads();
    if (tid < 64) atomicAdd(&g_ssum[b * K_ + tid], ssred[tid]);
}

// ---------------------------------------------------------------------------
// Kernel B: agg[128 d][64 k] = x @ s^T reducing FULL N=2048 (split-K=1).
// fp16 2-pass: acc += x_hi*s + x_lo*s. Grid (4, B) = 128 blocks, 1 wave.
#define PB 40
#define B_BUF  25600
#define B_SMEM (2 * B_BUF)

__global__ __launch_bounds__(256) void kB(const float* __restrict__ x) {
    extern __shared__ char sm[];
    const int b = blockIdx.y;
    const int d0 = blockIdx.x * 128;
    const int tid = threadIdx.x, lane = tid & 31, wid = tid >> 5;
    const uint32_t smb = smem_u32(sm);

    const int xrr = tid >> 3, xnn = (tid & 7) * 4;   // x: d row base, n offset
    const int sr = tid >> 2, sq = (tid & 3) * 16;    // S cp.async: row, 16B quarter
    const size_t gs_base = ((size_t)b * K_ + sr) * N_;

    float acc[8][4];
#pragma unroll
    for (int i = 0; i < 8; i++)
#pragma unroll
        for (int j = 0; j < 4; j++) acc[i][j] = 0.f;

    {
        uint32_t dst = smb + 20480 + sr * 80 + sq;
        CP16(dst, (const char*)&g_Sf[gs_base] + sq);
        CP_COMMIT();
    }
    float4 xbuf[4];
#pragma unroll
    for (int p = 0; p < 4; p++)
        xbuf[p] = *(const float4*)&x[((size_t)b * D_ + d0 + xrr + p * 32) * N_ + xnn];

    for (int c = 0; c < 64; c++) {
        char* bufc = sm + (c & 1) * B_BUF;
        __half* Xh = (__half*)(bufc);
        __half* Xl = (__half*)(bufc + 10240);

#pragma unroll
        for (int p = 0; p < 4; p++) {
            int rr = xrr + p * 32;
            uint32_t h0, l0, h1, l1;
            split2h(xbuf[p].x, xbuf[p].y, h0, l0);
            split2h(xbuf[p].z, xbuf[p].w, h1, l1);
            int off = rr * PB + xnn;
            *(uint32_t*)&Xh[off] = h0; *(uint32_t*)&Xh[off + 2] = h1;
            *(uint32_t*)&Xl[off] = l0; *(uint32_t*)&Xl[off + 2] = l1;
        }
        CP_WAIT0();
        __syncthreads();

        if (c < 63) {
            int n1 = (c + 1) * 32;
            uint32_t dst = smb + ((c + 1) & 1) * B_BUF + 20480 + sr * 80 + sq;
            CP16(dst, (const char*)&g_Sf[gs_base + n1] + sq);
            CP_COMMIT();
#pragma unroll
            for (int p = 0; p < 4; p++)
                xbuf[p] = *(const float4*)&x[((size_t)b * D_ + d0 + xrr + p * 32) * N_ + n1 + xnn];
        }

        const uint32_t xh_a = smb + (c & 1) * B_BUF;
        const uint32_t xl_a = xh_a + 10240;
        const uint32_t s_a  = xh_a + 20480;
#pragma unroll
        for (int ks = 0; ks < 2; ks++) {
            uint32_t ah[4], al[4];
            uint32_t aoff = (uint32_t)(((wid * 16 + (lane & 15)) * PB + ks * 16 + (lane >> 4) * 8) * 2);
            ldsm4(ah, xh_a + aoff);
            ldsm4(al, xl_a + aoff);
#pragma unroll
            for (int nf = 0; nf < 4; nf++) {
                uint32_t bh[4];
                uint32_t boff = (uint32_t)(((nf * 16 + (lane & 7) + ((lane >> 4) << 3)) * PB +
                                            ks * 16 + ((lane >> 3) & 1) * 8) * 2);
                ldsm4(bh, s_a + boff);
                mma_f16(acc[nf * 2],     ah, bh);
                mma_f16(acc[nf * 2],     al, bh);
                mma_f16(acc[nf * 2 + 1], ah, bh + 2);
                mma_f16(acc[nf * 2 + 1], al, bh + 2);
            }
        }
    }

    // direct non-atomic write of raw agg
    int g = lane >> 2, tg = lane & 3;
    int d = d0 + wid * 16 + g;
    float* base = &g_agg[((size_t)b * D_ + d) * K_];
#pragma unroll
    for (int nf = 0; nf < 8; nf++) {
        int cix = nf * 8 + tg * 2;
        base[cix]              = acc[nf][0];
        base[cix + 1]          = acc[nf][1];
        base[8 * K_ + cix]     = acc[nf][2];
        base[8 * K_ + cix + 1] = acc[nf][3];
    }
}

// ---------------------------------------------------------------------------
// Epilogue (float4 throughout, grid (4, B) = 128 blocks).
// k_epi1: v = agg - centers*ssum -> write back; colss via smem+global atomics.
__global__ __launch_bounds__(256) void k_epi1(const float* __restrict__ centers) {
    const int b = blockIdx.y;
    const int off0 = blockIdx.x * 8192;           // 128 d-rows * 64 k
    const int t = threadIdx.x;
    const int kb = (t & 15) * 4;                  // float4 k-base
    __shared__ float scols[64];
    if (t < 64) scols[t] = 0.f;
    __syncthreads();

    float s0 = g_ssum[b * K_ + kb], s1 = g_ssum[b * K_ + kb + 1];
    float s2 = g_ssum[b * K_ + kb + 2], s3 = g_ssum[b * K_ + kb + 3];
    const size_t base = (size_t)b * D_ * K_ + off0;
    float a0 = 0.f, a1 = 0.f, a2 = 0.f, a3 = 0.f;
#pragma unroll
    for (int i = 0; i < 8; i++) {
        int idx = (t + i * 256) * 4;
        float4 a = *(const float4*)&g_agg[base + idx];
        float4 cc = *(const float4*)&centers[off0 + idx];
        float4 v;
        v.x = a.x - cc.x * s0; v.y = a.y - cc.y * s1;
        v.z = a.z - cc.z * s2; v.w = a.w - cc.w * s3;
        *(float4*)&g_agg[base + idx] = v;
        a0 = fmaf(v.x, v.x, a0); a1 = fmaf(v.y, v.y, a1);
        a2 = fmaf(v.z, v.z, a2); a3 = fmaf(v.w, v.w, a3);
    }
    atomicAdd(&scols[kb],     a0);
    atomicAdd(&scols[kb + 1], a1);
    atomicAdd(&scols[kb + 2], a2);
    atomicAdd(&scols[kb + 3], a3);
    __syncthreads();
    if (t < 64) atomicAdd(&g_colss[b * K_ + t], scols[t]);
}

// k_epi2: mult from colss -> scale -> out (float4).
__global__ __launch_bounds__(256) void k_epi2(float* __restrict__ out) {
    const int b = blockIdx.y;
    const int off0 = blockIdx.x * 8192;
    const int t = threadIdx.x;
    const int kb = (t & 15) * 4;
    __shared__ float aft[64], invm[64];
    if (t < 64) {
        float ss = g_colss[b * K_ + t];
        float m = fmaxf(sqrtf(ss), 1e-12f);
        invm[t] = 1.f / m;
        aft[t] = ss / (m * m);
    }
    __syncthreads();
    if (t < 32) {
        float s = aft[t] + aft[t + 32];
#pragma unroll
        for (int o = 16; o > 0; o >>= 1) s += __shfl_xor_sync(0xffffffff, s, o);
        if (t == 0) aft[0] = 1.f / fmaxf(sqrtf(s), 1e-12f);
    }
    __syncthreads();
    const float g2 = aft[0];
    float m0 = g2 * invm[kb], m1 = g2 * invm[kb + 1];
    float m2 = g2 * invm[kb + 2], m3 = g2 * invm[kb + 3];
    const size_t base = (size_t)b * D_ * K_ + off0;
#pragma unroll
    for (int i = 0; i < 8; i++) {
        int idx = (t + i * 256) * 4;
        float4 v = *(const float4*)&g_agg[base + idx];
        v.x *= m0; v.y *= m1; v.z *= m2; v.w *= m3;
        *(float4*)&out[base + idx] = v;
    }
}

// ---------------------------------------------------------------------------
extern "C" void kernel_launch(void* const* d_in, const int* in_sizes, int n_in,
                              void* d_out, int out_size) {
    const float* x       = (const float*)d_in[0];  // [B, D, N]
    const float* W       = (const float*)d_in[1];  // [K, D]
    const float* centers = (const float*)d_in[2];  // [D, K]
    float* out = (float*)d_out;                    // [B, D*K]

    cudaFuncSetAttribute(kA, cudaFuncAttributeMaxDynamicSharedMemorySize, A_SMEM);
    cudaFuncSetAttribute(kB, cudaFuncAttributeMaxDynamicSharedMemorySize, B_SMEM);

    k_prep<<<32, 256>>>(W);
    dim3 gA(N_ / 128, B_);
    kA<<<gA, 256, A_SMEM>>>(x);
    dim3 gB(4, B_);            // 4 d-tiles, split-K=1, 128 blocks (1 wave)
    kB<<<gB, 256, B_SMEM>>>(x);
    dim3 gE(4, B_);
    k_epi1<<<gE, 256>>>(centers);
    k_epi2<<<gE, 256>>>(out);
}

// round 13
// speedup vs baseline: 1.2056x; 1.2056x over previous
#include <cuda_runtime.h>
#include <cuda_bf16.h>
#include <cuda_fp16.h>
#include <math.h>
#include <stdint.h>

#define B_ 32
#define D_ 512
#define N_ 2048
#define K_ 64

// ---------------------------------------------------------------------------
// Scratch (static device globals; no allocations allowed)
__device__ __align__(16) __half g_Wf[K_ * D_];                      // W fp16 (64 KB)
__device__ __align__(16) __half g_Sf[(size_t)B_ * K_ * N_];         // scores fp16 (8 MB)
__device__ __align__(16) float g_ssum[B_ * K_];
__device__ __align__(16) float g_colss[B_ * K_];
__device__ __align__(16) float g_aggp[4][(size_t)B_ * D_ * K_];     // split-K parts
__device__ __align__(16) float g_v[(size_t)B_ * D_ * K_];           // bias-corrected v

// ---------------------------------------------------------------------------
__device__ __forceinline__ uint32_t smem_u32(const void* p) {
    uint32_t a;
    asm("{ .reg .u64 t; cvta.to.shared.u64 t, %1; cvt.u32.u64 %0, t; }" : "=r"(a) : "l"(p));
    return a;
}
__device__ __forceinline__ void ldsm4(uint32_t* r, uint32_t a) {
    asm volatile("ldmatrix.sync.aligned.m8n8.x4.shared.b16 {%0,%1,%2,%3}, [%4];"
                 : "=r"(r[0]), "=r"(r[1]), "=r"(r[2]), "=r"(r[3]) : "r"(a));
}
__device__ __forceinline__ void ldsm4t(uint32_t* r, uint32_t a) {
    asm volatile("ldmatrix.sync.aligned.m8n8.x4.trans.shared.b16 {%0,%1,%2,%3}, [%4];"
                 : "=r"(r[0]), "=r"(r[1]), "=r"(r[2]), "=r"(r[3]) : "r"(a));
}
__device__ __forceinline__ void mma_f16(float* c, const uint32_t* a, const uint32_t* b) {
    asm volatile("mma.sync.aligned.m16n8k16.row.col.f32.f16.f16.f32 "
                 "{%0,%1,%2,%3}, {%4,%5,%6,%7}, {%8,%9}, {%0,%1,%2,%3};"
                 : "+f"(c[0]), "+f"(c[1]), "+f"(c[2]), "+f"(c[3])
                 : "r"(a[0]), "r"(a[1]), "r"(a[2]), "r"(a[3]), "r"(b[0]), "r"(b[1]));
}
// fp16 hi/lo split of two floats
__device__ __forceinline__ void split2h(float x, float y, uint32_t& hi, uint32_t& lo) {
    __half2 h = __floats2half2_rn(x, y);
    float2 f = __half22float2(h);
    __half2 l = __floats2half2_rn(x - f.x, y - f.y);
    hi = *(uint32_t*)&h;
    lo = *(uint32_t*)&l;
}
#define CP16(dst, src) asm volatile("cp.async.cg.shared.global [%0], [%1], 16;" :: "r"(dst), "l"(src))
#define CP_COMMIT()    asm volatile("cp.async.commit_group;")
#define CP_WAIT0()     asm volatile("cp.async.wait_group 0;" ::: "memory")

// ---------------------------------------------------------------------------
__global__ void k_prep(const float* __restrict__ W) {
    int t = blockIdx.x * blockDim.x + threadIdx.x;
    if (t < B_ * K_) { g_ssum[t] = 0.f; g_colss[t] = 0.f; }
    if (t < K_ * D_ / 4) {
        float4 v = *(const float4*)&W[t * 4];
        __half2 a = __floats2half2_rn(v.x, v.y);
        __half2 b = __floats2half2_rn(v.z, v.w);
        *(uint2*)&g_Wf[t * 4] = make_uint2(*(uint32_t*)&a, *(uint32_t*)&b);
    }
}

// ---------------------------------------------------------------------------
// Kernel A: logits[64 k][128 n] = W @ x_tile (reduce D=512), fp16 2-pass:
// acc += W*x_hi + W*x_lo. W fp16 via cp.async; x split in-regs.
#define PA 40
#define PX 136
#define A_BUF  22528
#define A_ST2  34048
#define A_SMEM (34048 + 16384)

__global__ __launch_bounds__(256) void kA(const float* __restrict__ x) {
    extern __shared__ char sm[];
    const int b = blockIdx.y, n0 = blockIdx.x * 128;
    const int tid = threadIdx.x, lane = tid & 31, wid = tid >> 5;
    const int wm = wid & 3, wn = wid >> 2;
    const uint32_t smb = smem_u32(sm);

    const int wk4 = tid >> 2, wq = (tid & 3) * 8;    // W cp.async: k row, d offset(8 halfs)
    const int xnn = lane * 4;                         // x: n offset

    float acc[8][4];
#pragma unroll
    for (int i = 0; i < 8; i++)
#pragma unroll
        for (int j = 0; j < 4; j++) acc[i][j] = 0.f;

    {
        uint32_t dst = smb + wk4 * 80 + wq * 2;
        CP16(dst, &g_Wf[wk4 * D_ + wq]);
        CP_COMMIT();
    }
    float4 xbuf[4];
#pragma unroll
    for (int p = 0; p < 4; p++)
        xbuf[p] = *(const float4*)&x[((size_t)b * D_ + wid + p * 8) * N_ + n0 + xnn];

    for (int c = 0; c < 16; c++) {
        char* bufc = sm + (c & 1) * A_BUF;
        __half* Xh = (__half*)(bufc + 5120);
        __half* Xl = (__half*)(bufc + 13824);

#pragma unroll
        for (int p = 0; p < 4; p++) {
            int dd = wid + p * 8;
            uint32_t h0, l0, h1, l1;
            split2h(xbuf[p].x, xbuf[p].y, h0, l0);
            split2h(xbuf[p].z, xbuf[p].w, h1, l1);
            int off = dd * PX + xnn;
            *(uint32_t*)&Xh[off] = h0; *(uint32_t*)&Xh[off + 2] = h1;
            *(uint32_t*)&Xl[off] = l0; *(uint32_t*)&Xl[off + 2] = l1;
        }
        CP_WAIT0();
        __syncthreads();

        if (c < 15) {
            int d1 = (c + 1) * 32;
            uint32_t dst = smb + ((c + 1) & 1) * A_BUF + wk4 * 80 + wq * 2;
            CP16(dst, &g_Wf[wk4 * D_ + d1 + wq]);
            CP_COMMIT();
#pragma unroll
            for (int p = 0; p < 4; p++)
                xbuf[p] = *(const float4*)&x[((size_t)b * D_ + d1 + wid + p * 8) * N_ + n0 + xnn];
        }

        const uint32_t w_a  = smb + (c & 1) * A_BUF;
        const uint32_t xh_a = w_a + 5120;
        const uint32_t xl_a = w_a + 13824;
#pragma unroll
        for (int ks = 0; ks < 2; ks++) {
            uint32_t aw[4];
            uint32_t aoff = (uint32_t)(((wm * 16 + (lane & 15)) * PA + ks * 16 + (lane >> 4) * 8) * 2);
            ldsm4(aw, w_a + aoff);
#pragma unroll
            for (int nf = 0; nf < 4; nf++) {
                uint32_t bh[4], bl[4];
                uint32_t boff = (uint32_t)(((ks * 16 + (lane & 15)) * PX +
                                            wn * 64 + nf * 16 + (lane >> 4) * 8) * 2);
                ldsm4t(bh, xh_a + boff);
                ldsm4t(bl, xl_a + boff);
                mma_f16(acc[nf * 2],     aw, bh);
                mma_f16(acc[nf * 2],     aw, bl);
                mma_f16(acc[nf * 2 + 1], aw, bh + 2);
                mma_f16(acc[nf * 2 + 1], aw, bl + 2);
            }
        }
    }
    __syncthreads();

    // stash logits tile [64][132] f32
    float* st = (float*)sm;
    {
        int g = lane >> 2, tg = lane & 3;
        int r0 = wm * 16 + g;
#pragma unroll
        for (int nf = 0; nf < 8; nf++) {
            int cix = wn * 64 + nf * 8 + tg * 2;
            st[r0 * 132 + cix]           = acc[nf][0];
            st[r0 * 132 + cix + 1]       = acc[nf][1];
            st[(r0 + 8) * 132 + cix]     = acc[nf][2];
            st[(r0 + 8) * 132 + cix + 1] = acc[nf][3];
        }
    }
    float* ssred = (float*)(sm + 33792);
    __half* st2 = (__half*)(sm + A_ST2);
    __syncthreads();

    // softmax over k per column; quantize scores to fp16
    if (tid < 128) {
        int col = tid;
        float m = -1e30f;
#pragma unroll
        for (int k = 0; k < 64; k++) m = fmaxf(m, st[k * 132 + col]);
        float s = 0.f;
#pragma unroll
        for (int k = 0; k < 64; k++) {
            float e = __expf(st[k * 132 + col] - m);
            st[k * 132 + col] = e;
            s += e;
        }
        float inv = 1.f / s;
#pragma unroll
        for (int k = 0; k < 64; k++)
            st2[k * 128 + col] = __float2half_rn(st[k * 132 + col] * inv);
    }
    __syncthreads();

    // coalesced fp16 score writes + piggybacked per-row ssum (quantized values)
#pragma unroll
    for (int r = 0; r < 8; r++) {
        int row = wid * 8 + r;
        uint2 v = ((const uint2*)&st2[row * 128])[lane];
        ((uint2*)&g_Sf[((size_t)b * K_ + row) * N_ + n0])[lane] = v;
        __half2 h0 = *(__half2*)&v.x, h1 = *(__half2*)&v.y;
        float2 f0 = __half22float2(h0), f1 = __half22float2(h1);
        float ws = (f0.x + f0.y) + (f1.x + f1.y);
#pragma unroll
        for (int o = 16; o > 0; o >>= 1) ws += __shfl_xor_sync(0xffffffff, ws, o);
        if (lane == 0) ssred[row] = ws;
    }
    __syncthreads();
    if (tid < 64) atomicAdd(&g_ssum[b * K_ + tid], ssred[tid]);
}

// ---------------------------------------------------------------------------
// Kernel B: agg_part[sp][128 d][64 k] = x @ s^T (reduce 512 n), fp16 2-pass.
// Split-K 4 (512 blocks -> 3.5/SM; cross-block latency hiding proven in R11).
#define PB 40
#define B_BUF  25600
#define B_SMEM (2 * B_BUF)

__global__ __launch_bounds__(256) void kB(const float* __restrict__ x) {
    extern __shared__ char sm[];
    const int b = blockIdx.y;
    const int d0 = (blockIdx.x & 3) * 128;
    const int sp = blockIdx.x >> 2;
    const int spn = sp * 512;
    const int tid = threadIdx.x, lane = tid & 31, wid = tid >> 5;
    const uint32_t smb = smem_u32(sm);

    const int xrr = tid >> 3, xnn = (tid & 7) * 4;   // x: d row base, n offset
    const int sr = tid >> 2, sq = (tid & 3) * 16;    // S cp.async: row, 16B quarter
    const size_t gs_base = ((size_t)b * K_ + sr) * N_ + spn;

    float acc[8][4];
#pragma unroll
    for (int i = 0; i < 8; i++)
#pragma unroll
        for (int j = 0; j < 4; j++) acc[i][j] = 0.f;

    {
        uint32_t dst = smb + 20480 + sr * 80 + sq;
        CP16(dst, (const char*)&g_Sf[gs_base] + sq);
        CP_COMMIT();
    }
    float4 xbuf[4];
#pragma unroll
    for (int p = 0; p < 4; p++)
        xbuf[p] = *(const float4*)&x[((size_t)b * D_ + d0 + xrr + p * 32) * N_ + spn + xnn];

    for (int c = 0; c < 16; c++) {
        char* bufc = sm + (c & 1) * B_BUF;
        __half* Xh = (__half*)(bufc);
        __half* Xl = (__half*)(bufc + 10240);

#pragma unroll
        for (int p = 0; p < 4; p++) {
            int rr = xrr + p * 32;
            uint32_t h0, l0, h1, l1;
            split2h(xbuf[p].x, xbuf[p].y, h0, l0);
            split2h(xbuf[p].z, xbuf[p].w, h1, l1);
            int off = rr * PB + xnn;
            *(uint32_t*)&Xh[off] = h0; *(uint32_t*)&Xh[off + 2] = h1;
            *(uint32_t*)&Xl[off] = l0; *(uint32_t*)&Xl[off + 2] = l1;
        }
        CP_WAIT0();
        __syncthreads();

        if (c < 15) {
            int n1 = (c + 1) * 32;
            uint32_t dst = smb + ((c + 1) & 1) * B_BUF + 20480 + sr * 80 + sq;
            CP16(dst, (const char*)&g_Sf[gs_base + n1] + sq);
            CP_COMMIT();
#pragma unroll
            for (int p = 0; p < 4; p++)
                xbuf[p] = *(const float4*)&x[((size_t)b * D_ + d0 + xrr + p * 32) * N_ + spn + n1 + xnn];
        }

        const uint32_t xh_a = smb + (c & 1) * B_BUF;
        const uint32_t xl_a = xh_a + 10240;
        const uint32_t s_a  = xh_a + 20480;
#pragma unroll
        for (int ks = 0; ks < 2; ks++) {
            uint32_t ah[4], al[4];
            uint32_t aoff = (uint32_t)(((wid * 16 + (lane & 15)) * PB + ks * 16 + (lane >> 4) * 8) * 2);
            ldsm4(ah, xh_a + aoff);
            ldsm4(al, xl_a + aoff);
#pragma unroll
            for (int nf = 0; nf < 4; nf++) {
                uint32_t bh[4];
                uint32_t boff = (uint32_t)(((nf * 16 + (lane & 7) + ((lane >> 4) << 3)) * PB +
                                            ks * 16 + ((lane >> 3) & 1) * 8) * 2);
                ldsm4(bh, s_a + boff);
                mma_f16(acc[nf * 2],     ah, bh);
                mma_f16(acc[nf * 2],     al, bh);
                mma_f16(acc[nf * 2 + 1], ah, bh + 2);
                mma_f16(acc[nf * 2 + 1], al, bh + 2);
            }
        }
    }

    int g = lane >> 2, tg = lane & 3;
    int d = d0 + wid * 16 + g;
    float* base = &g_aggp[sp][((size_t)b * D_ + d) * K_];
#pragma unroll
    for (int nf = 0; nf < 8; nf++) {
        int cix = nf * 8 + tg * 2;
        base[cix]              = acc[nf][0];
        base[cix + 1]          = acc[nf][1];
        base[8 * K_ + cix]     = acc[nf][2];
        base[8 * K_ + cix + 1] = acc[nf][3];
    }
}

// ---------------------------------------------------------------------------
// Epilogue (float4 + deep MLP, grid (8, B) = 256 blocks).
// k_epi1: v = sum(4 parts) - centers*ssum -> g_v; colss via smem+global atomics.
__global__ __launch_bounds__(256) void k_epi1(const float* __restrict__ centers) {
    const int b = blockIdx.y;
    const int off0 = blockIdx.x * 4096;           // 64 d-rows * 64 k
    const int t = threadIdx.x;
    const int kb = (t & 15) * 4;                  // float4 k-base
    __shared__ float scols[64];
    if (t < 64) scols[t] = 0.f;
    __syncthreads();

    float s0 = g_ssum[b * K_ + kb], s1 = g_ssum[b * K_ + kb + 1];
    float s2 = g_ssum[b * K_ + kb + 2], s3 = g_ssum[b * K_ + kb + 3];
    const size_t base = (size_t)b * D_ * K_ + off0;
    float a0 = 0.f, a1 = 0.f, a2 = 0.f, a3 = 0.f;
#pragma unroll
    for (int i = 0; i < 4; i++) {
        int idx = (t + i * 256) * 4;
        float4 p0 = *(const float4*)&g_aggp[0][base + idx];
        float4 p1 = *(const float4*)&g_aggp[1][base + idx];
        float4 p2 = *(const float4*)&g_aggp[2][base + idx];
        float4 p3 = *(const float4*)&g_aggp[3][base + idx];
        float4 cc = *(const float4*)&centers[off0 + idx];
        float4 v;
        v.x = (p0.x + p1.x) + (p2.x + p3.x) - cc.x * s0;
        v.y = (p0.y + p1.y) + (p2.y + p3.y) - cc.y * s1;
        v.z = (p0.z + p1.z) + (p2.z + p3.z) - cc.z * s2;
        v.w = (p0.w + p1.w) + (p2.w + p3.w) - cc.w * s3;
        *(float4*)&g_v[base + idx] = v;
        a0 = fmaf(v.x, v.x, a0); a1 = fmaf(v.y, v.y, a1);
        a2 = fmaf(v.z, v.z, a2); a3 = fmaf(v.w, v.w, a3);
    }
    atomicAdd(&scols[kb],     a0);
    atomicAdd(&scols[kb + 1], a1);
    atomicAdd(&scols[kb + 2], a2);
    atomicAdd(&scols[kb + 3], a3);
    __syncthreads();
    if (t < 64) atomicAdd(&g_colss[b * K_ + t], scols[t]);
}

// k_epi2: mult from colss -> scale -> out (float4).
__global__ __launch_bounds__(256) void k_epi2(float* __restrict__ out) {
    const int b = blockIdx.y;
    const int off0 = blockIdx.x * 4096;
    const int t = threadIdx.x;
    const int kb = (t & 15) * 4;
    __shared__ float aft[64], invm[64];
    if (t < 64) {
        float ss = g_colss[b * K_ + t];
        float m = fmaxf(sqrtf(ss), 1e-12f);
        invm[t] = 1.f / m;
        aft[t] = ss / (m * m);
    }
    __syncthreads();
    if (t < 32) {
        float s = aft[t] + aft[t + 32];
#pragma unroll
        for (int o = 16; o > 0; o >>= 1) s += __shfl_xor_sync(0xffffffff, s, o);
        if (t == 0) aft[0] = 1.f / fmaxf(sqrtf(s), 1e-12f);
    }
    __syncthreads();
    const float g2 = aft[0];
    float m0 = g2 * invm[kb], m1 = g2 * invm[kb + 1];
    float m2 = g2 * invm[kb + 2], m3 = g2 * invm[kb + 3];
    const size_t base = (size_t)b * D_ * K_ + off0;
#pragma unroll
    for (int i = 0; i < 4; i++) {
        int idx = (t + i * 256) * 4;
        float4 v = *(const float4*)&g_v[base + idx];
        v.x *= m0; v.y *= m1; v.z *= m2; v.w *= m3;
        *(float4*)&out[base + idx] = v;
    }
}

// ---------------------------------------------------------------------------
extern "C" void kernel_launch(void* const* d_in, const int* in_sizes, int n_in,
                              void* d_out, int out_size) {
    const float* x       = (const float*)d_in[0];  // [B, D, N]
    const float* W       = (const float*)d_in[1];  // [K, D]
    const float* centers = (const float*)d_in[2];  // [D, K]
    float* out = (float*)d_out;                    // [B, D*K]

    cudaFuncSetAttribute(kA, cudaFuncAttributeMaxDynamicSharedMemorySize, A_SMEM);
    cudaFuncSetAttribute(kB, cudaFuncAttributeMaxDynamicSharedMemorySize, B_SMEM);

    k_prep<<<32, 256>>>(W);
    dim3 gA(N_ / 128, B_);
    kA<<<gA, 256, A_SMEM>>>(x);
    dim3 gB(16, B_);           // 4 d-tiles x 4 n-splits = 512 blocks
    kB<<<gB, 256, B_SMEM>>>(x);
    dim3 gE(8, B_);
    k_epi1<<<gE, 256>>>(centers);
    k_epi2<<<gE, 256>>>(out);
}

// round 14
// speedup vs baseline: 1.3127x; 1.0888x over previous
#include <cuda_runtime.h>
#include <cuda_bf16.h>
#include <cuda_fp16.h>
#include <math.h>
#include <stdint.h>

#define B_ 32
#define D_ 512
#define N_ 2048
#define K_ 64

// ---------------------------------------------------------------------------
// Scratch (static device globals; no allocations allowed)
__device__ __align__(16) __half g_Wf[K_ * D_];                      // W fp16 (64 KB)
__device__ __align__(16) __half g_Sf[(size_t)B_ * K_ * N_];         // scores fp16 (8 MB)
__device__ __align__(16) float g_ssum[B_ * K_];
__device__ __align__(16) float g_colss[B_ * K_];
__device__ __align__(16) float g_aggp[4][(size_t)B_ * D_ * K_];     // split-K parts
__device__ __align__(16) float g_v[(size_t)B_ * D_ * K_];           // bias-corrected v

// ---------------------------------------------------------------------------
__device__ __forceinline__ uint32_t smem_u32(const void* p) {
    uint32_t a;
    asm("{ .reg .u64 t; cvta.to.shared.u64 t, %1; cvt.u32.u64 %0, t; }" : "=r"(a) : "l"(p));
    return a;
}
__device__ __forceinline__ void ldsm4(uint32_t* r, uint32_t a) {
    asm volatile("ldmatrix.sync.aligned.m8n8.x4.shared.b16 {%0,%1,%2,%3}, [%4];"
                 : "=r"(r[0]), "=r"(r[1]), "=r"(r[2]), "=r"(r[3]) : "r"(a));
}
__device__ __forceinline__ void ldsm4t(uint32_t* r, uint32_t a) {
    asm volatile("ldmatrix.sync.aligned.m8n8.x4.trans.shared.b16 {%0,%1,%2,%3}, [%4];"
                 : "=r"(r[0]), "=r"(r[1]), "=r"(r[2]), "=r"(r[3]) : "r"(a));
}
__device__ __forceinline__ void mma_f16(float* c, const uint32_t* a, const uint32_t* b) {
    asm volatile("mma.sync.aligned.m16n8k16.row.col.f32.f16.f16.f32 "
                 "{%0,%1,%2,%3}, {%4,%5,%6,%7}, {%8,%9}, {%0,%1,%2,%3};"
                 : "+f"(c[0]), "+f"(c[1]), "+f"(c[2]), "+f"(c[3])
                 : "r"(a[0]), "r"(a[1]), "r"(a[2]), "r"(a[3]), "r"(b[0]), "r"(b[1]));
}
__device__ __forceinline__ uint32_t packh2(float x, float y) {
    __half2 h = __floats2half2_rn(x, y);
    return *(uint32_t*)&h;
}
#define CP16(dst, src) asm volatile("cp.async.cg.shared.global [%0], [%1], 16;" :: "r"(dst), "l"(src))
#define CP_COMMIT()    asm volatile("cp.async.commit_group;")
#define CP_WAIT0()     asm volatile("cp.async.wait_group 0;" ::: "memory")

// ---------------------------------------------------------------------------
__global__ void k_prep(const float* __restrict__ W) {
    int t = blockIdx.x * blockDim.x + threadIdx.x;
    if (t < B_ * K_) { g_ssum[t] = 0.f; g_colss[t] = 0.f; }
    if (t < K_ * D_ / 4) {
        float4 v = *(const float4*)&W[t * 4];
        *(uint2*)&g_Wf[t * 4] = make_uint2(packh2(v.x, v.y), packh2(v.z, v.w));
    }
}

// ---------------------------------------------------------------------------
// Kernel A: logits[64 k][128 n] = W @ x_tile (reduce D=512), fp16 1-pass.
// W fp16 via cp.async; x converted to single fp16 plane in-regs.
// smem stage: Wf 5120 | Xh 8704 = 13824; two stages.
// post-loop reuse: st f32[64][132] @0 | ssred @33792 | st2 fp16 @34048
#define PA 40
#define PX 136
#define A_BUF  13824
#define A_ST2  34048
#define A_SMEM (34048 + 16384)

__global__ __launch_bounds__(256) void kA(const float* __restrict__ x) {
    extern __shared__ char sm[];
    const int b = blockIdx.y, n0 = blockIdx.x * 128;
    const int tid = threadIdx.x, lane = tid & 31, wid = tid >> 5;
    const int wm = wid & 3, wn = wid >> 2;
    const uint32_t smb = smem_u32(sm);

    const int wk4 = tid >> 2, wq = (tid & 3) * 8;    // W cp.async: k row, d offset(8 halfs)
    const int xnn = lane * 4;                         // x: n offset

    float acc[8][4];
#pragma unroll
    for (int i = 0; i < 8; i++)
#pragma unroll
        for (int j = 0; j < 4; j++) acc[i][j] = 0.f;

    {
        uint32_t dst = smb + wk4 * 80 + wq * 2;
        CP16(dst, &g_Wf[wk4 * D_ + wq]);
        CP_COMMIT();
    }
    float4 xbuf[4];
#pragma unroll
    for (int p = 0; p < 4; p++)
        xbuf[p] = *(const float4*)&x[((size_t)b * D_ + wid + p * 8) * N_ + n0 + xnn];

    for (int c = 0; c < 16; c++) {
        char* bufc = sm + (c & 1) * A_BUF;
        __half* Xh = (__half*)(bufc + 5120);

#pragma unroll
        for (int p = 0; p < 4; p++) {
            int dd = wid + p * 8;
            int off = dd * PX + xnn;
            *(uint32_t*)&Xh[off]     = packh2(xbuf[p].x, xbuf[p].y);
            *(uint32_t*)&Xh[off + 2] = packh2(xbuf[p].z, xbuf[p].w);
        }
        CP_WAIT0();
        __syncthreads();

        if (c < 15) {
            int d1 = (c + 1) * 32;
            uint32_t dst = smb + ((c + 1) & 1) * A_BUF + wk4 * 80 + wq * 2;
            CP16(dst, &g_Wf[wk4 * D_ + d1 + wq]);
            CP_COMMIT();
#pragma unroll
            for (int p = 0; p < 4; p++)
                xbuf[p] = *(const float4*)&x[((size_t)b * D_ + d1 + wid + p * 8) * N_ + n0 + xnn];
        }

        const uint32_t w_a  = smb + (c & 1) * A_BUF;
        const uint32_t xh_a = w_a + 5120;
#pragma unroll
        for (int ks = 0; ks < 2; ks++) {
            uint32_t aw[4];
            uint32_t aoff = (uint32_t)(((wm * 16 + (lane & 15)) * PA + ks * 16 + (lane >> 4) * 8) * 2);
            ldsm4(aw, w_a + aoff);
#pragma unroll
            for (int nf = 0; nf < 4; nf++) {
                uint32_t bh[4];
                uint32_t boff = (uint32_t)(((ks * 16 + (lane & 15)) * PX +
                                            wn * 64 + nf * 16 + (lane >> 4) * 8) * 2);
                ldsm4t(bh, xh_a + boff);
                mma_f16(acc[nf * 2],     aw, bh);
                mma_f16(acc[nf * 2 + 1], aw, bh + 2);
            }
        }
    }
    __syncthreads();

    // stash logits tile [64][132] f32
    float* st = (float*)sm;
    {
        int g = lane >> 2, tg = lane & 3;
        int r0 = wm * 16 + g;
#pragma unroll
        for (int nf = 0; nf < 8; nf++) {
            int cix = wn * 64 + nf * 8 + tg * 2;
            st[r0 * 132 + cix]           = acc[nf][0];
            st[r0 * 132 + cix + 1]       = acc[nf][1];
            st[(r0 + 8) * 132 + cix]     = acc[nf][2];
            st[(r0 + 8) * 132 + cix + 1] = acc[nf][3];
        }
    }
    float* ssred = (float*)(sm + 33792);
    __half* st2 = (__half*)(sm + A_ST2);
    __syncthreads();

    // softmax over k per column; quantize scores to fp16
    if (tid < 128) {
        int col = tid;
        float m = -1e30f;
#pragma unroll
        for (int k = 0; k < 64; k++) m = fmaxf(m, st[k * 132 + col]);
        float s = 0.f;
#pragma unroll
        for (int k = 0; k < 64; k++) {
            float e = __expf(st[k * 132 + col] - m);
            st[k * 132 + col] = e;
            s += e;
        }
        float inv = 1.f / s;
#pragma unroll
        for (int k = 0; k < 64; k++)
            st2[k * 128 + col] = __float2half_rn(st[k * 132 + col] * inv);
    }
    __syncthreads();

    // coalesced fp16 score writes + piggybacked per-row ssum (quantized values)
#pragma unroll
    for (int r = 0; r < 8; r++) {
        int row = wid * 8 + r;
        uint2 v = ((const uint2*)&st2[row * 128])[lane];
        ((uint2*)&g_Sf[((size_t)b * K_ + row) * N_ + n0])[lane] = v;
        __half2 h0 = *(__half2*)&v.x, h1 = *(__half2*)&v.y;
        float2 f0 = __half22float2(h0), f1 = __half22float2(h1);
        float ws = (f0.x + f0.y) + (f1.x + f1.y);
#pragma unroll
        for (int o = 16; o > 0; o >>= 1) ws += __shfl_xor_sync(0xffffffff, ws, o);
        if (lane == 0) ssred[row] = ws;
    }
    __syncthreads();
    if (tid < 64) atomicAdd(&g_ssum[b * K_ + tid], ssred[tid]);
}

// ---------------------------------------------------------------------------
// Kernel B: agg_part[sp][128 d][64 k] = x @ s^T (reduce 512 n), fp16 1-pass.
// Split-K 4 (512 blocks). smem stage: Xh 10240 | S 5120 = 15360; two stages.
#define PB 40
#define B_BUF  15360
#define B_SMEM (2 * B_BUF)

__global__ __launch_bounds__(256) void kB(const float* __restrict__ x) {
    extern __shared__ char sm[];
    const int b = blockIdx.y;
    const int d0 = (blockIdx.x & 3) * 128;
    const int sp = blockIdx.x >> 2;
    const int spn = sp * 512;
    const int tid = threadIdx.x, lane = tid & 31, wid = tid >> 5;
    const uint32_t smb = smem_u32(sm);

    const int xrr = tid >> 3, xnn = (tid & 7) * 4;   // x: d row base, n offset
    const int sr = tid >> 2, sq = (tid & 3) * 16;    // S cp.async: row, 16B quarter
    const size_t gs_base = ((size_t)b * K_ + sr) * N_ + spn;

    float acc[8][4];
#pragma unroll
    for (int i = 0; i < 8; i++)
#pragma unroll
        for (int j = 0; j < 4; j++) acc[i][j] = 0.f;

    {
        uint32_t dst = smb + 10240 + sr * 80 + sq;
        CP16(dst, (const char*)&g_Sf[gs_base] + sq);
        CP_COMMIT();
    }
    float4 xbuf[4];
#pragma unroll
    for (int p = 0; p < 4; p++)
        xbuf[p] = *(const float4*)&x[((size_t)b * D_ + d0 + xrr + p * 32) * N_ + spn + xnn];

    for (int c = 0; c < 16; c++) {
        char* bufc = sm + (c & 1) * B_BUF;
        __half* Xh = (__half*)(bufc);

#pragma unroll
        for (int p = 0; p < 4; p++) {
            int rr = xrr + p * 32;
            int off = rr * PB + xnn;
            *(uint32_t*)&Xh[off]     = packh2(xbuf[p].x, xbuf[p].y);
            *(uint32_t*)&Xh[off + 2] = packh2(xbuf[p].z, xbuf[p].w);
        }
        CP_WAIT0();
        __syncthreads();

        if (c < 15) {
            int n1 = (c + 1) * 32;
            uint32_t dst = smb + ((c + 1) & 1) * B_BUF + 10240 + sr * 80 + sq;
            CP16(dst, (const char*)&g_Sf[gs_base + n1] + sq);
            CP_COMMIT();
#pragma unroll
            for (int p = 0; p < 4; p++)
                xbuf[p] = *(const float4*)&x[((size_t)b * D_ + d0 + xrr + p * 32) * N_ + spn + n1 + xnn];
        }

        const uint32_t xh_a = smb + (c & 1) * B_BUF;
        const uint32_t s_a  = xh_a + 10240;
#pragma unroll
        for (int ks = 0; ks < 2; ks++) {
            uint32_t ah[4];
            uint32_t aoff = (uint32_t)(((wid * 16 + (lane & 15)) * PB + ks * 16 + (lane >> 4) * 8) * 2);
            ldsm4(ah, xh_a + aoff);
#pragma unroll
            for (int nf = 0; nf < 4; nf++) {
                uint32_t bh[4];
                uint32_t boff = (uint32_t)(((nf * 16 + (lane & 7) + ((lane >> 4) << 3)) * PB +
                                            ks * 16 + ((lane >> 3) & 1) * 8) * 2);
                ldsm4(bh, s_a + boff);
                mma_f16(acc[nf * 2],     ah, bh);
                mma_f16(acc[nf * 2 + 1], ah, bh + 2);
            }
        }
    }

    int g = lane >> 2, tg = lane & 3;
    int d = d0 + wid * 16 + g;
    float* base = &g_aggp[sp][((size_t)b * D_ + d) * K_];
#pragma unroll
    for (int nf = 0; nf < 8; nf++) {
        int cix = nf * 8 + tg * 2;
        base[cix]              = acc[nf][0];
        base[cix + 1]          = acc[nf][1];
        base[8 * K_ + cix]     = acc[nf][2];
        base[8 * K_ + cix + 1] = acc[nf][3];
    }
}

// ---------------------------------------------------------------------------
// Epilogue (float4 + deep MLP, grid (8, B) = 256 blocks).
__global__ __launch_bounds__(256) void k_epi1(const float* __restrict__ centers) {
    const int b = blockIdx.y;
    const int off0 = blockIdx.x * 4096;           // 64 d-rows * 64 k
    const int t = threadIdx.x;
    const int kb = (t & 15) * 4;
    __shared__ float scols[64];
    if (t < 64) scols[t] = 0.f;
    __syncthreads();

    float s0 = g_ssum[b * K_ + kb], s1 = g_ssum[b * K_ + kb + 1];
    float s2 = g_ssum[b * K_ + kb + 2], s3 = g_ssum[b * K_ + kb + 3];
    const size_t base = (size_t)b * D_ * K_ + off0;
    float a0 = 0.f, a1 = 0.f, a2 = 0.f, a3 = 0.f;
#pragma unroll
    for (int i = 0; i < 4; i++) {
        int idx = (t + i * 256) * 4;
        float4 p0 = *(const float4*)&g_aggp[0][base + idx];
        float4 p1 = *(const float4*)&g_aggp[1][base + idx];
        float4 p2 = *(const float4*)&g_aggp[2][base + idx];
        float4 p3 = *(const float4*)&g_aggp[3][base + idx];
        float4 cc = *(const float4*)&centers[off0 + idx];
        float4 v;
        v.x = (p0.x + p1.x) + (p2.x + p3.x) - cc.x * s0;
        v.y = (p0.y + p1.y) + (p2.y + p3.y) - cc.y * s1;
        v.z = (p0.z + p1.z) + (p2.z + p3.z) - cc.z * s2;
        v.w = (p0.w + p1.w) + (p2.w + p3.w) - cc.w * s3;
        *(float4*)&g_v[base + idx] = v;
        a0 = fmaf(v.x, v.x, a0); a1 = fmaf(v.y, v.y, a1);
        a2 = fmaf(v.z, v.z, a2); a3 = fmaf(v.w, v.w, a3);
    }
    atomicAdd(&scols[kb],     a0);
    atomicAdd(&scols[kb + 1], a1);
    atomicAdd(&scols[kb + 2], a2);
    atomicAdd(&scols[kb + 3], a3);
    __syncthreads();
    if (t < 64) atomicAdd(&g_colss[b * K_ + t], scols[t]);
}

__global__ __launch_bounds__(256) void k_epi2(float* __restrict__ out) {
    const int b = blockIdx.y;
    const int off0 = blockIdx.x * 4096;
    const int t = threadIdx.x;
    const int kb = (t & 15) * 4;
    __shared__ float aft[64], invm[64];
    if (t < 64) {
        float ss = g_colss[b * K_ + t];
        float m = fmaxf(sqrtf(ss), 1e-12f);
        invm[t] = 1.f / m;
        aft[t] = ss / (m * m);
    }
    __syncthreads();
    if (t < 32) {
        float s = aft[t] + aft[t + 32];
#pragma unroll
        for (int o = 16; o > 0; o >>= 1) s += __shfl_xor_sync(0xffffffff, s, o);
        if (t == 0) aft[0] = 1.f / fmaxf(sqrtf(s), 1e-12f);
    }
    __syncthreads();
    const float g2 = aft[0];
    float m0 = g2 * invm[kb], m1 = g2 * invm[kb + 1];
    float m2 = g2 * invm[kb + 2], m3 = g2 * invm[kb + 3];
    const size_t base = (size_t)b * D_ * K_ + off0;
#pragma unroll
    for (int i = 0; i < 4; i++) {
        int idx = (t + i * 256) * 4;
        float4 v = *(const float4*)&g_v[base + idx];
        v.x *= m0; v.y *= m1; v.z *= m2; v.w *= m3;
        *(float4*)&out[base + idx] = v;
    }
}

// ---------------------------------------------------------------------------
extern "C" void kernel_launch(void* const* d_in, const int* in_sizes, int n_in,
                              void* d_out, int out_size) {
    const float* x       = (const float*)d_in[0];  // [B, D, N]
    const float* W       = (const float*)d_in[1];  // [K, D]
    const float* centers = (const float*)d_in[2];  // [D, K]
    float* out = (float*)d_out;                    // [B, D*K]

    cudaFuncSetAttribute(kA, cudaFuncAttributeMaxDynamicSharedMemorySize, A_SMEM);
    cudaFuncSetAttribute(kB, cudaFuncAttributeMaxDynamicSharedMemorySize, B_SMEM);

    k_prep<<<32, 256>>>(W);
    dim3 gA(N_ / 128, B_);
    kA<<<gA, 256, A_SMEM>>>(x);
    dim3 gB(16, B_);           // 4 d-tiles x 4 n-splits = 512 blocks
    kB<<<gB, 256, B_SMEM>>>(x);
    dim3 gE(8, B_);
    k_epi1<<<gE, 256>>>(centers);
    k_epi2<<<gE, 256>>>(out);
}

// round 15
// speedup vs baseline: 1.5184x; 1.1567x over previous
#include <cuda_runtime.h>
#include <cuda_bf16.h>
#include <cuda_fp16.h>
#include <math.h>
#include <stdint.h>

#define B_ 32
#define D_ 512
#define N_ 2048
#define K_ 64

// ---------------------------------------------------------------------------
// Scratch (static device globals; no allocations allowed)
__device__ __align__(16) __half g_Wf[K_ * D_];                      // W fp16 (64 KB)
__device__ __align__(16) __half g_Sf[(size_t)B_ * K_ * N_];         // scores fp16 (8 MB)
__device__ __align__(16) float g_ssum[B_ * K_];
__device__ __align__(16) float g_colss[B_ * K_];
__device__ __align__(16) float g_aggp[4][(size_t)B_ * D_ * K_];     // split-K parts
__device__ __align__(16) float g_v[(size_t)B_ * D_ * K_];           // bias-corrected v

// ---------------------------------------------------------------------------
__device__ __forceinline__ uint32_t smem_u32(const void* p) {
    uint32_t a;
    asm("{ .reg .u64 t; cvta.to.shared.u64 t, %1; cvt.u32.u64 %0, t; }" : "=r"(a) : "l"(p));
    return a;
}
__device__ __forceinline__ void ldsm4(uint32_t* r, uint32_t a) {
    asm volatile("ldmatrix.sync.aligned.m8n8.x4.shared.b16 {%0,%1,%2,%3}, [%4];"
                 : "=r"(r[0]), "=r"(r[1]), "=r"(r[2]), "=r"(r[3]) : "r"(a));
}
__device__ __forceinline__ void ldsm4t(uint32_t* r, uint32_t a) {
    asm volatile("ldmatrix.sync.aligned.m8n8.x4.trans.shared.b16 {%0,%1,%2,%3}, [%4];"
                 : "=r"(r[0]), "=r"(r[1]), "=r"(r[2]), "=r"(r[3]) : "r"(a));
}
__device__ __forceinline__ void mma_f16(float* c, const uint32_t* a, const uint32_t* b) {
    asm volatile("mma.sync.aligned.m16n8k16.row.col.f32.f16.f16.f32 "
                 "{%0,%1,%2,%3}, {%4,%5,%6,%7}, {%8,%9}, {%0,%1,%2,%3};"
                 : "+f"(c[0]), "+f"(c[1]), "+f"(c[2]), "+f"(c[3])
                 : "r"(a[0]), "r"(a[1]), "r"(a[2]), "r"(a[3]), "r"(b[0]), "r"(b[1]));
}
__device__ __forceinline__ uint32_t packh2(float x, float y) {
    __half2 h = __floats2half2_rn(x, y);
    return *(uint32_t*)&h;
}
#define CP16(dst, src) asm volatile("cp.async.cg.shared.global [%0], [%1], 16;" :: "r"(dst), "l"(src))
#define CP_COMMIT()    asm volatile("cp.async.commit_group;")
#define CP_WAIT0()     asm volatile("cp.async.wait_group 0;" ::: "memory")

// ---------------------------------------------------------------------------
__global__ void k_prep(const float* __restrict__ W) {
    int t = blockIdx.x * blockDim.x + threadIdx.x;
    if (t < B_ * K_) { g_ssum[t] = 0.f; g_colss[t] = 0.f; }
    if (t < K_ * D_ / 4) {
        float4 v = *(const float4*)&W[t * 4];
        *(uint2*)&g_Wf[t * 4] = make_uint2(packh2(v.x, v.y), packh2(v.z, v.w));
    }
}

// ---------------------------------------------------------------------------
// Kernel A: logits[64 k][128 n] = W @ x_tile (reduce D=512), fp16 1-pass,
// 64-wide D-chunks (8 iterations, 1 sync each).
// smem stage: W 64x72h (9216) | X 64x136h (17408) = 26624; two stages.
// post-loop reuse: st f32[64][132] @0 | ssred @33792 | st2 fp16 @34048
#define PA 72
#define PX 136
#define A_BUF  26624
#define A_ST2  34048
#define A_SMEM (50432 + 8192)

__global__ __launch_bounds__(256) void kA(const float* __restrict__ x) {
    extern __shared__ char sm[];
    const int b = blockIdx.y, n0 = blockIdx.x * 128;
    const int tid = threadIdx.x, lane = tid & 31, wid = tid >> 5;
    const int wm = wid & 3, wn = wid >> 2;
    const uint32_t smb = smem_u32(sm);

    const int wrow = tid >> 2, wc16 = (tid & 3) * 16;  // W cp.async: k row, 16-half col
    const int xnn = lane * 4;                           // x: n offset

    float acc[8][4];
#pragma unroll
    for (int i = 0; i < 8; i++)
#pragma unroll
        for (int j = 0; j < 4; j++) acc[i][j] = 0.f;

    {
        uint32_t dst = smb + wrow * 144 + (tid & 3) * 32;
        CP16(dst,      &g_Wf[wrow * D_ + wc16]);
        CP16(dst + 16, &g_Wf[wrow * D_ + wc16 + 8]);
        CP_COMMIT();
    }
    float4 xbuf[8];
#pragma unroll
    for (int p = 0; p < 8; p++)
        xbuf[p] = *(const float4*)&x[((size_t)b * D_ + wid + p * 8) * N_ + n0 + xnn];

    for (int c = 0; c < 8; c++) {
        char* bufc = sm + (c & 1) * A_BUF;
        __half* Xh = (__half*)(bufc + 9216);

#pragma unroll
        for (int p = 0; p < 8; p++) {
            int dd = wid + p * 8;
            int off = dd * PX + xnn;
            *(uint32_t*)&Xh[off]     = packh2(xbuf[p].x, xbuf[p].y);
            *(uint32_t*)&Xh[off + 2] = packh2(xbuf[p].z, xbuf[p].w);
        }
        CP_WAIT0();
        __syncthreads();

        if (c < 7) {
            int d1 = (c + 1) * 64;
            uint32_t dst = smb + ((c + 1) & 1) * A_BUF + wrow * 144 + (tid & 3) * 32;
            CP16(dst,      &g_Wf[wrow * D_ + d1 + wc16]);
            CP16(dst + 16, &g_Wf[wrow * D_ + d1 + wc16 + 8]);
            CP_COMMIT();
#pragma unroll
            for (int p = 0; p < 8; p++)
                xbuf[p] = *(const float4*)&x[((size_t)b * D_ + d1 + wid + p * 8) * N_ + n0 + xnn];
        }

        const uint32_t w_a  = smb + (c & 1) * A_BUF;
        const uint32_t xh_a = w_a + 9216;
#pragma unroll
        for (int ks = 0; ks < 4; ks++) {
            uint32_t aw[4];
            uint32_t aoff = (uint32_t)(((wm * 16 + (lane & 15)) * PA + ks * 16 + (lane >> 4) * 8) * 2);
            ldsm4(aw, w_a + aoff);
#pragma unroll
            for (int nf = 0; nf < 4; nf++) {
                uint32_t bh[4];
                uint32_t boff = (uint32_t)(((ks * 16 + (lane & 15)) * PX +
                                            wn * 64 + nf * 16 + (lane >> 4) * 8) * 2);
                ldsm4t(bh, xh_a + boff);
                mma_f16(acc[nf * 2],     aw, bh);
                mma_f16(acc[nf * 2 + 1], aw, bh + 2);
            }
        }
    }
    __syncthreads();

    // stash logits tile [64][132] f32
    float* st = (float*)sm;
    {
        int g = lane >> 2, tg = lane & 3;
        int r0 = wm * 16 + g;
#pragma unroll
        for (int nf = 0; nf < 8; nf++) {
            int cix = wn * 64 + nf * 8 + tg * 2;
            st[r0 * 132 + cix]           = acc[nf][0];
            st[r0 * 132 + cix + 1]       = acc[nf][1];
            st[(r0 + 8) * 132 + cix]     = acc[nf][2];
            st[(r0 + 8) * 132 + cix + 1] = acc[nf][3];
        }
    }
    float* ssred = (float*)(sm + 33792);
    __half* st2 = (__half*)(sm + A_ST2);
    __syncthreads();

    // softmax over k per column; quantize scores to fp16
    if (tid < 128) {
        int col = tid;
        float m = -1e30f;
#pragma unroll
        for (int k = 0; k < 64; k++) m = fmaxf(m, st[k * 132 + col]);
        float s = 0.f;
#pragma unroll
        for (int k = 0; k < 64; k++) {
            float e = __expf(st[k * 132 + col] - m);
            st[k * 132 + col] = e;
            s += e;
        }
        float inv = 1.f / s;
#pragma unroll
        for (int k = 0; k < 64; k++)
            st2[k * 128 + col] = __float2half_rn(st[k * 132 + col] * inv);
    }
    __syncthreads();

    // coalesced fp16 score writes + piggybacked per-row ssum (quantized values)
#pragma unroll
    for (int r = 0; r < 8; r++) {
        int row = wid * 8 + r;
        uint2 v = ((const uint2*)&st2[row * 128])[lane];
        ((uint2*)&g_Sf[((size_t)b * K_ + row) * N_ + n0])[lane] = v;
        __half2 h0 = *(__half2*)&v.x, h1 = *(__half2*)&v.y;
        float2 f0 = __half22float2(h0), f1 = __half22float2(h1);
        float ws = (f0.x + f0.y) + (f1.x + f1.y);
#pragma unroll
        for (int o = 16; o > 0; o >>= 1) ws += __shfl_xor_sync(0xffffffff, ws, o);
        if (lane == 0) ssred[row] = ws;
    }
    __syncthreads();
    if (tid < 64) atomicAdd(&g_ssum[b * K_ + tid], ssred[tid]);
}

// ---------------------------------------------------------------------------
// Kernel B: agg_part[sp][128 d][64 k] = x @ s^T (reduce 512 n), fp16 1-pass,
// 64-wide n-chunks (8 iterations, 1 sync each). Split-K 4 (512 blocks).
// smem stage: X 128x72h (18432) | S 64x72h (9216) = 27648; two stages.
#define PB 72
#define B_BUF  27648
#define B_SMEM (2 * B_BUF)

__global__ __launch_bounds__(256) void kB(const float* __restrict__ x) {
    extern __shared__ char sm[];
    const int b = blockIdx.y;
    const int d0 = (blockIdx.x & 3) * 128;
    const int sp = blockIdx.x >> 2;
    const int spn = sp * 512;
    const int tid = threadIdx.x, lane = tid & 31, wid = tid >> 5;
    const uint32_t smb = smem_u32(sm);

    const int xrr = tid >> 4, xnn = (tid & 15) * 4;  // x: d row base, n offset
    const int srow = tid >> 2, sc16 = (tid & 3) * 16; // S cp.async: k row, 16-half col
    const size_t gs_base = ((size_t)b * K_ + srow) * N_ + spn;

    float acc[8][4];
#pragma unroll
    for (int i = 0; i < 8; i++)
#pragma unroll
        for (int j = 0; j < 4; j++) acc[i][j] = 0.f;

    {
        uint32_t dst = smb + 18432 + srow * 144 + (tid & 3) * 32;
        CP16(dst,      &g_Sf[gs_base + sc16]);
        CP16(dst + 16, &g_Sf[gs_base + sc16 + 8]);
        CP_COMMIT();
    }
    float4 xbuf[8];
#pragma unroll
    for (int p = 0; p < 8; p++)
        xbuf[p] = *(const float4*)&x[((size_t)b * D_ + d0 + xrr + p * 16) * N_ + spn + xnn];

    for (int c = 0; c < 8; c++) {
        char* bufc = sm + (c & 1) * B_BUF;
        __half* Xh = (__half*)(bufc);

#pragma unroll
        for (int p = 0; p < 8; p++) {
            int rr = xrr + p * 16;
            int off = rr * PB + xnn;
            *(uint32_t*)&Xh[off]     = packh2(xbuf[p].x, xbuf[p].y);
            *(uint32_t*)&Xh[off + 2] = packh2(xbuf[p].z, xbuf[p].w);
        }
        CP_WAIT0();
        __syncthreads();

        if (c < 7) {
            int n1 = (c + 1) * 64;
            uint32_t dst = smb + ((c + 1) & 1) * B_BUF + 18432 + srow * 144 + (tid & 3) * 32;
            CP16(dst,      &g_Sf[gs_base + n1 + sc16]);
            CP16(dst + 16, &g_Sf[gs_base + n1 + sc16 + 8]);
            CP_COMMIT();
#pragma unroll
            for (int p = 0; p < 8; p++)
                xbuf[p] = *(const float4*)&x[((size_t)b * D_ + d0 + xrr + p * 16) * N_ + spn + n1 + xnn];
        }

        const uint32_t xh_a = smb + (c & 1) * B_BUF;
        const uint32_t s_a  = xh_a + 18432;
#pragma unroll
        for (int ks = 0; ks < 4; ks++) {
            uint32_t ah[4];
            uint32_t aoff = (uint32_t)(((wid * 16 + (lane & 15)) * PB + ks * 16 + (lane >> 4) * 8) * 2);
            ldsm4(ah, xh_a + aoff);
#pragma unroll
            for (int nf = 0; nf < 4; nf++) {
                uint32_t bh[4];
                uint32_t boff = (uint32_t)(((nf * 16 + (lane & 7) + ((lane >> 4) << 3)) * PB +
                                            ks * 16 + ((lane >> 3) & 1) * 8) * 2);
                ldsm4(bh, s_a + boff);
                mma_f16(acc[nf * 2],     ah, bh);
                mma_f16(acc[nf * 2 + 1], ah, bh + 2);
            }
        }
    }

    int g = lane >> 2, tg = lane & 3;
    int d = d0 + wid * 16 + g;
    float* base = &g_aggp[sp][((size_t)b * D_ + d) * K_];
#pragma unroll
    for (int nf = 0; nf < 8; nf++) {
        int cix = nf * 8 + tg * 2;
        base[cix]              = acc[nf][0];
        base[cix + 1]          = acc[nf][1];
        base[8 * K_ + cix]     = acc[nf][2];
        base[8 * K_ + cix + 1] = acc[nf][3];
    }
}

// ---------------------------------------------------------------------------
// Epilogue (float4 + deep MLP, grid (8, B) = 256 blocks).
__global__ __launch_bounds__(256) void k_epi1(const float* __restrict__ centers) {
    const int b = blockIdx.y;
    const int off0 = blockIdx.x * 4096;           // 64 d-rows * 64 k
    const int t = threadIdx.x;
    const int kb = (t & 15) * 4;
    __shared__ float scols[64];
    if (t < 64) scols[t] = 0.f;
    __syncthreads();

    float s0 = g_ssum[b * K_ + kb], s1 = g_ssum[b * K_ + kb + 1];
    float s2 = g_ssum[b * K_ + kb + 2], s3 = g_ssum[b * K_ + kb + 3];
    const size_t base = (size_t)b * D_ * K_ + off0;
    float a0 = 0.f, a1 = 0.f, a2 = 0.f, a3 = 0.f;
#pragma unroll
    for (int i = 0; i < 4; i++) {
        int idx = (t + i * 256) * 4;
        float4 p0 = *(const float4*)&g_aggp[0][base + idx];
        float4 p1 = *(const float4*)&g_aggp[1][base + idx];
        float4 p2 = *(const float4*)&g_aggp[2][base + idx];
        float4 p3 = *(const float4*)&g_aggp[3][base + idx];
        float4 cc = *(const float4*)&centers[off0 + idx];
        float4 v;
        v.x = (p0.x + p1.x) + (p2.x + p3.x) - cc.x * s0;
        v.y = (p0.y + p1.y) + (p2.y + p3.y) - cc.y * s1;
        v.z = (p0.z + p1.z) + (p2.z + p3.z) - cc.z * s2;
        v.w = (p0.w + p1.w) + (p2.w + p3.w) - cc.w * s3;
        *(float4*)&g_v[base + idx] = v;
        a0 = fmaf(v.x, v.x, a0); a1 = fmaf(v.y, v.y, a1);
        a2 = fmaf(v.z, v.z, a2); a3 = fmaf(v.w, v.w, a3);
    }
    atomicAdd(&scols[kb],     a0);
    atomicAdd(&scols[kb + 1], a1);
    atomicAdd(&scols[kb + 2], a2);
    atomicAdd(&scols[kb + 3], a3);
    __syncthreads();
    if (t < 64) atomicAdd(&g_colss[b * K_ + t], scols[t]);
}

__global__ __launch_bounds__(256) void k_epi2(float* __restrict__ out) {
    const int b = blockIdx.y;
    const int off0 = blockIdx.x * 4096;
    const int t = threadIdx.x;
    const int kb = (t & 15) * 4;
    __shared__ float aft[64], invm[64];
    if (t < 64) {
        float ss = g_colss[b * K_ + t];
        float m = fmaxf(sqrtf(ss), 1e-12f);
        invm[t] = 1.f / m;
        aft[t] = ss / (m * m);
    }
    __syncthreads();
    if (t < 32) {
        float s = aft[t] + aft[t + 32];
#pragma unroll
        for (int o = 16; o > 0; o >>= 1) s += __shfl_xor_sync(0xffffffff, s, o);
        if (t == 0) aft[0] = 1.f / fmaxf(sqrtf(s), 1e-12f);
    }
    __syncthreads();
    const float g2 = aft[0];
    float m0 = g2 * invm[kb], m1 = g2 * invm[kb + 1];
    float m2 = g2 * invm[kb + 2], m3 = g2 * invm[kb + 3];
    const size_t base = (size_t)b * D_ * K_ + off0;
#pragma unroll
    for (int i = 0; i < 4; i++) {
        int idx = (t + i * 256) * 4;
        float4 v = *(const float4*)&g_v[base + idx];
        v.x *= m0; v.y *= m1; v.z *= m2; v.w *= m3;
        *(float4*)&out[base + idx] = v;
    }
}

// ---------------------------------------------------------------------------
extern "C" void kernel_launch(void* const* d_in, const int* in_sizes, int n_in,
                              void* d_out, int out_size) {
    const float* x       = (const float*)d_in[0];  // [B, D, N]
    const float* W       = (const float*)d_in[1];  // [K, D]
    const float* centers = (const float*)d_in[2];  // [D, K]
    float* out = (float*)d_out;                    // [B, D*K]

    cudaFuncSetAttribute(kA, cudaFuncAttributeMaxDynamicSharedMemorySize, A_SMEM);
    cudaFuncSetAttribute(kB, cudaFuncAttributeMaxDynamicSharedMemorySize, B_SMEM);

    k_prep<<<32, 256>>>(W);
    dim3 gA(N_ / 128, B_);
    kA<<<gA, 256, A_SMEM>>>(x);
    dim3 gB(16, B_);           // 4 d-tiles x 4 n-splits = 512 blocks
    kB<<<gB, 256, B_SMEM>>>(x);
    dim3 gE(8, B_);
    k_epi1<<<gE, 256>>>(centers);
    k_epi2<<<gE, 256>>>(out);
}